// round 8
// baseline (speedup 1.0000x reference)
#include <cuda_runtime.h>
#include <cuda_bf16.h>
#include <math.h>

// Problem constants
#define Bb   512
#define Cc   64
#define Nn   32
#define Vv   100
#define EMB  32
#define HID  64
#define Ee   256
#define Tt   37
#define EMBP (EMB + 4)   // padded row length for transposed M (36 floats = 144B, 16B-aligned rows)

// Precomputed per-launch constants (16B-aligned: read via float4)
__device__ __align__(16) float g_A[Nn * Nn];       // normalized adjacency (row = dst)
__device__ __align__(16) float g_MzT[HID * EMBP];  // (W_z @ L_z[:HID])^T, padded
__device__ __align__(16) float g_MhT[HID * EMBP];  // (W_h @ L_h[:HID])^T, padded
__device__ float g_cz[HID];                        // b_z @ L_z[:HID] + lb_z
__device__ float g_ch[HID];                        // b_h @ L_h[:HID] + lb_h
__device__ float g_cumP[Tt + 1];                   // prefix sums of softmax(att)

// ---------------------------------------------------------------------------
// Prelude: 1 block, 1024 threads (runs alone -> minimize its serial latency).
// Deterministic: per-row ownership, fixed order, no float atomics.
// ---------------------------------------------------------------------------
__global__ void __launch_bounds__(1024) precompute_kernel(
    const int*   __restrict__ edge,   // (2, E)
    const float* __restrict__ Wz,     // (EMB, HID)
    const float* __restrict__ bz,     // (HID,)
    const float* __restrict__ Wh,     // (EMB, HID)
    const float* __restrict__ bh,     // (HID,)
    const float* __restrict__ Lz,     // (2*HID, HID) -> first HID rows used
    const float* __restrict__ lbz,    // (HID,)
    const float* __restrict__ Lh,     // (2*HID, HID)
    const float* __restrict__ lbh,    // (HID,)
    const float* __restrict__ att)    // (T,)
{
    __shared__ int   s_src[Ee + Nn];
    __shared__ int   s_dst[Ee + Nn];
    __shared__ float s_dinv[Nn];

    const int t = threadIdx.x;

    // Load edges + append self loops
    for (int e = t; e < Ee + Nn; e += 1024) {
        s_src[e] = (e < Ee) ? edge[e]       : (e - Ee);
        s_dst[e] = (e < Ee) ? edge[Ee + e]  : (e - Ee);
    }
    for (int o = t; o < Nn * Nn; o += 1024) g_A[o] = 0.0f;
    // Zero the pad columns of the transposed M arrays
    for (int o = t; o < HID * EMBP; o += 1024) {
        if ((o % EMBP) >= EMB) { g_MzT[o] = 0.0f; g_MhT[o] = 0.0f; }
    }
    __syncthreads();

    // Degree + dinv: one node per thread (warp 0)
    if (t < Nn) {
        float d = 0.0f;
        for (int e = 0; e < Ee + Nn; e++)
            if (s_dst[e] == t) d += 1.0f;
        s_dinv[t] = (d > 0.0f) ? rsqrtf(d) : 0.0f;
    }
    __syncthreads();

    // A[dst][src] += dinv[src]*dinv[dst]  (row ownership -> deterministic)
    if (t < Nn) {
        for (int e = 0; e < Ee + Nn; e++) {
            if (s_dst[e] == t) {
                const int s = s_src[e];
                g_A[t * Nn + s] += s_dinv[s] * s_dinv[t];
            }
        }
    }

    // M^T[j][e] = sum_k W[e][k] * L[k][j] : 2048 outputs, 2 per thread.
    for (int o = t; o < EMB * HID; o += 1024) {
        const int e = o / HID, j = o % HID;
        float az = 0.0f, ah = 0.0f;
        #pragma unroll 8
        for (int k = 0; k < HID; k++) {
            az += Wz[e * HID + k] * Lz[k * HID + j];
            ah += Wh[e * HID + k] * Lh[k * HID + j];
        }
        g_MzT[j * EMBP + e] = az;
        g_MhT[j * EMBP + e] = ah;
    }

    // Folded biases
    if (t < HID) {
        float cz = lbz[t], ch = lbh[t];
        for (int k = 0; k < HID; k++) {
            cz += bz[k] * Lz[k * HID + t];
            ch += bh[k] * Lh[k * HID + t];
        }
        g_cz[t] = cz;
        g_ch[t] = ch;
    }

    // Softmax prefix table (serial: 37 elems)
    if (t == 0) {
        float m = att[0];
        for (int i = 1; i < Tt; i++) m = fmaxf(m, att[i]);
        float ex[Tt];
        float s = 0.0f;
        for (int i = 0; i < Tt; i++) { ex[i] = expf(att[i] - m); s += ex[i]; }
        const float inv = 1.0f / s;
        float acc = 0.0f;
        g_cumP[0] = 0.0f;
        for (int i = 0; i < Tt; i++) { acc += ex[i] * inv; g_cumP[i + 1] = acc; }
    }
}

// ---------------------------------------------------------------------------
// Main: one CTA (256 threads) per batch row.
//   pooled[b] = mean_n( w0*cell(ad[b]) + w1*cell(dis[b]) )   [H never stored]
//   cell(X)   = (1 - sigmoid(A@X@Mz + cz)) * tanh(A@X@Mh + ch)
//   out[b]    = relu(pooled @ Wc1 + bc1) @ Wc2 + bc2
//
// __launch_bounds__(256, 4): pins regs <= 64 so 4 CTAs/SM -> grid 512 runs
// in ONE wave (148*4 = 592 concurrent CTAs). Occupancy loss here would cost
// a full second wave; a couple of spills cannot.
// ---------------------------------------------------------------------------
__global__ void __launch_bounds__(256, 4) main_kernel(
    const int*   __restrict__ x_batch,  // (B, C)
    const int*   __restrict__ LOS,      // (B,)
    const float* __restrict__ emb,      // (C, V, EMB)
    const float* __restrict__ Wc1,      // (HID, 2*HID)
    const float* __restrict__ bc1,      // (2*HID,)
    const float* __restrict__ Wc2,      // (2*HID, 1)
    const float* __restrict__ bc2,      // (1,)
    float*       __restrict__ out)      // (B, 1)
{
    __shared__ __align__(16) float sX[Cc][EMB];      // embeddings (ad 0..31, dis 32..63)
    __shared__ __align__(16) float sA[Nn][Nn];       // adjacency
    __shared__ __align__(16) float sMzT[HID][EMBP];  // folded weights, transposed+padded
    __shared__ __align__(16) float sMhT[HID][EMBP];
    __shared__ __align__(16) float sU[2][Nn][EMB];   // A @ X per branch
    __shared__ float sPool[4][HID];                  // per-group pool partials
    __shared__ float sPooled[HID];
    __shared__ float sRed[2 * HID];

    const int b = blockIdx.x;
    const int t = threadIdx.x;

    // Issue branch-weight loads FIRST so their latency overlaps staging.
    int L = LOS[b];
    L = min(max(L, 0), Tt);
    const float w0 = g_cumP[L];            // weight on 'ad' branch
    const float w1 = g_cumP[Tt] - w0;      // weight on 'dis' branch

    // Stage constants into shared, vectorized.
    // HID*EMBP = 2304 floats = 576 float4 per matrix.
    {
        const float4* gA4  = (const float4*)g_A;     // 256 float4
        const float4* gMz4 = (const float4*)g_MzT;   // 576 float4
        const float4* gMh4 = (const float4*)g_MhT;
        float4* sA4  = (float4*)&sA[0][0];
        float4* sMz4 = (float4*)&sMzT[0][0];
        float4* sMh4 = (float4*)&sMhT[0][0];
        sA4[t] = gA4[t];
        #pragma unroll
        for (int i = 0; i < 2; i++) {
            sMz4[t + 256 * i] = gMz4[t + 256 * i];
            sMh4[t + 256 * i] = gMh4[t + 256 * i];
        }
        if (t < 576 - 512) {
            sMz4[t + 512] = gMz4[t + 512];
            sMh4[t + 512] = gMh4[t + 512];
        }
    }

    // Gather embeddings: 512 float4, 2 per thread. Index loaded directly
    // (warp-broadcast LDG) -> no staging barrier needed before gather.
    {
        const float4* emb4 = (const float4*)emb;
        float4* sX4 = (float4*)&sX[0][0];
        #pragma unroll
        for (int i = 0; i < 2; i++) {
            const int o = t + 256 * i;        // 0..511
            const int c = o >> 3, q = o & 7;
            const int idx = x_batch[b * Cc + c];
            sX4[o] = emb4[(c * Vv + idx) * (EMB / 4) + q];
        }
    }
    __syncthreads();  // sX, sA, sM* ready

    // U = A @ X, both branches. Thread owns (n = t>>3, q = t&7) and computes
    // float4 U[br][n][4q..4q+3] for br = 0 and 1, sharing one A-row hoist.
    // X consumed as LDS.128 (8 distinct addrs/warp, broadcast, conflict-free).
    {
        const int n = t >> 3;
        const int q = t & 7;
        const float4* arow = (const float4*)&sA[n][0];
        float4 a[8];
        #pragma unroll
        for (int mt = 0; mt < 8; mt++) a[mt] = arow[mt];

        #pragma unroll
        for (int br = 0; br < 2; br++) {
            float4 acc = make_float4(0.0f, 0.0f, 0.0f, 0.0f);
            #pragma unroll
            for (int mt = 0; mt < 8; mt++) {
                #pragma unroll
                for (int mm = 0; mm < 4; mm++) {
                    const float am = (mm == 0) ? a[mt].x : (mm == 1) ? a[mt].y
                                   : (mm == 2) ? a[mt].z : a[mt].w;
                    const float4 x4 = *(const float4*)&sX[br * Nn + mt * 4 + mm][4 * q];
                    acc.x += am * x4.x;
                    acc.y += am * x4.y;
                    acc.z += am * x4.z;
                    acc.w += am * x4.w;
                }
            }
            *(float4*)&sU[br][n][4 * q] = acc;
        }
    }
    __syncthreads();  // sU ready

    // H phase fused with pooling: thread t -> column j = t&63,
    // nodes n = (t>>6) + 4i, i=0..7. M read as LDS.128 from the transposed
    // padded layout (conflict-free: 4j mod 32 bank groups per phase).
    {
        const int j  = t & 63;
        const int g  = t >> 6;
        const float cz = g_cz[j], ch = g_ch[j];
        float poolAcc = 0.0f;

        #pragma unroll
        for (int br = 0; br < 2; br++) {
            const float w = (br == 0) ? w0 : w1;
            float az[8], ah[8];
            #pragma unroll
            for (int i = 0; i < 8; i++) { az[i] = cz; ah[i] = ch; }

            #pragma unroll
            for (int kt = 0; kt < EMB / 4; kt++) {
                const int e0 = kt * 4;
                const float4 mz4 = *(const float4*)&sMzT[j][e0];
                const float4 mh4 = *(const float4*)&sMhT[j][e0];
                #pragma unroll
                for (int i = 0; i < 8; i++) {
                    const int n = g + 4 * i;
                    const float4 u4 = *(const float4*)&sU[br][n][e0];  // broadcast
                    az[i] += u4.x * mz4.x + u4.y * mz4.y + u4.z * mz4.z + u4.w * mz4.w;
                    ah[i] += u4.x * mh4.x + u4.y * mh4.y + u4.z * mh4.z + u4.w * mh4.w;
                }
            }

            #pragma unroll
            for (int i = 0; i < 8; i++) {
                // (1 - sigmoid(az)) = 1/(1+e^{az});  tanh(x) = 1 - 2/(1+e^{2x})
                const float omz = __fdividef(1.0f, 1.0f + __expf(az[i]));
                const float th  = 1.0f - __fdividef(2.0f, 1.0f + __expf(2.0f * ah[i]));
                poolAcc += w * omz * th;
            }
        }

        sPool[g][j] = poolAcc;
    }
    __syncthreads();  // sPool ready

    // pooled[j] = (sum of 4 group partials) / N
    if (t < HID) {
        sPooled[t] = (sPool[0][t] + sPool[1][t] + sPool[2][t] + sPool[3][t])
                     * (1.0f / (float)Nn);
    }
    __syncthreads();

    // classifier: hidden (128) -> scalar
    float partial = 0.0f;
    if (t < 2 * HID) {
        float h = bc1[t];
        #pragma unroll 8
        for (int j = 0; j < HID; j++)
            h += sPooled[j] * Wc1[j * (2 * HID) + t];
        partial = fmaxf(h, 0.0f) * Wc2[t];
    }
    if (t < 2 * HID) sRed[t] = partial;
    __syncthreads();

    if (t < 32) {
        float s = sRed[t] + sRed[t + 32] + sRed[t + 64] + sRed[t + 96];
        #pragma unroll
        for (int off = 16; off > 0; off >>= 1)
            s += __shfl_down_sync(0xFFFFFFFFu, s, off);
        if (t == 0) out[b] = s + bc2[0];
    }
}

// ---------------------------------------------------------------------------
// Launch
// ---------------------------------------------------------------------------
extern "C" void kernel_launch(void* const* d_in, const int* in_sizes, int n_in,
                              void* d_out, int out_size)
{
    const int*   x_batch = (const int*)  d_in[0];
    const int*   LOS     = (const int*)  d_in[1];
    const int*   edge    = (const int*)  d_in[2];
    const float* emb     = (const float*)d_in[3];
    const float* Wz      = (const float*)d_in[4];
    const float* bz      = (const float*)d_in[5];
    // d_in[6] = W_r, d_in[7] = b_r : dead (H0*R == 0 because H0 == 0)
    const float* Wh      = (const float*)d_in[8];
    const float* bh      = (const float*)d_in[9];
    const float* Lz      = (const float*)d_in[10];
    const float* lbz     = (const float*)d_in[11];
    // d_in[12] = L_r, d_in[13] = lb_r : dead
    const float* Lh      = (const float*)d_in[14];
    const float* lbh     = (const float*)d_in[15];
    const float* att     = (const float*)d_in[16];
    const float* Wc1     = (const float*)d_in[17];
    const float* bc1     = (const float*)d_in[18];
    const float* Wc2     = (const float*)d_in[19];
    const float* bc2     = (const float*)d_in[20];

    precompute_kernel<<<1, 1024>>>(edge, Wz, bz, Wh, bh, Lz, lbz, Lh, lbh, att);
    main_kernel<<<Bb, 256>>>(x_batch, LOS, emb, Wc1, bc1, Wc2, bc2, (float*)d_out);
}

// round 9
// speedup vs baseline: 1.0876x; 1.0876x over previous
#include <cuda_runtime.h>
#include <cuda_bf16.h>
#include <math.h>

// Problem constants
#define Bb   512
#define Cc   64
#define Nn   32
#define Vv   100
#define EMB  32
#define HID  64
#define Ee   256
#define Tt   37
#define EMBP (EMB + 4)   // padded row length for transposed M (36 floats = 144B, 16B-aligned rows)

// Precomputed per-launch constants (16B-aligned: read via float4)
__device__ __align__(16) float g_A[Nn * Nn];       // normalized adjacency (row = dst)
__device__ __align__(16) float g_MzT[HID * EMBP];  // (W_z @ L_z[:HID])^T, padded
__device__ __align__(16) float g_MhT[HID * EMBP];  // (W_h @ L_h[:HID])^T, padded
__device__ float g_cz[HID];                        // b_z @ L_z[:HID] + lb_z
__device__ float g_ch[HID];                        // b_h @ L_h[:HID] + lb_h
__device__ float g_cumP[Tt + 1];                   // prefix sums of softmax(att)

// ---------------------------------------------------------------------------
// Prelude: 1 block, 1024 threads, fully parallel.
// Determinism: adjacency built from INTEGER edge counts (order-invariant
// atomics), then A = cnt * dinv*dinv computed per-element. Softmax prefix
// via warp shuffle scan. M-GEMM: 4 outputs/thread sharing L-column loads.
// ---------------------------------------------------------------------------
__global__ void __launch_bounds__(1024) precompute_kernel(
    const int*   __restrict__ edge,   // (2, E)
    const float* __restrict__ Wz,     // (EMB, HID)
    const float* __restrict__ bz,     // (HID,)
    const float* __restrict__ Wh,     // (EMB, HID)
    const float* __restrict__ bh,     // (HID,)
    const float* __restrict__ Lz,     // (2*HID, HID) -> first HID rows used
    const float* __restrict__ lbz,    // (HID,)
    const float* __restrict__ Lh,     // (2*HID, HID)
    const float* __restrict__ lbh,    // (HID,)
    const float* __restrict__ att)    // (T,)
{
    __shared__ int   sCnt[Nn * Nn];   // edge multiplicity per (dst,src)
    __shared__ int   sDeg[Nn];
    __shared__ float sDinv[Nn];

    const int t = threadIdx.x;

    if (t < Nn * Nn) sCnt[t] = 0;
    if (t < Nn) sDeg[t] = 0;
    __syncthreads();

    // One edge per thread; self loops appended. Integer atomics: deterministic.
    if (t < Ee) {
        const int s = edge[t];
        const int d = edge[Ee + t];
        atomicAdd(&sCnt[d * Nn + s], 1);
        atomicAdd(&sDeg[d], 1);
    } else if (t < Ee + Nn) {
        const int n = t - Ee;
        atomicAdd(&sCnt[n * Nn + n], 1);
        atomicAdd(&sDeg[n], 1);
    }
    __syncthreads();

    if (t < Nn) sDinv[t] = (sDeg[t] > 0) ? rsqrtf((float)sDeg[t]) : 0.0f;
    __syncthreads();

    // A[d][s] = cnt * dinv[s] * dinv[d], one element per thread.
    if (t < Nn * Nn) {
        const int d = t >> 5, s = t & 31;
        g_A[t] = (float)sCnt[t] * sDinv[s] * sDinv[d];
    }

    // Zero pad columns of transposed M (row t for t < HID)
    if (t < HID) {
        #pragma unroll
        for (int p = EMB; p < EMBP; p++) {
            g_MzT[t * EMBP + p] = 0.0f;
            g_MhT[t * EMBP + p] = 0.0f;
        }
    }

    // M-GEMM: thread t covers (e0 = t>>6, j = t&63) and (e1 = e0+16, same j)
    // for BOTH matrices -> L-column loads shared by two W rows.
    {
        const int j  = t & 63;
        const int e0 = t >> 6;        // 0..15
        const int e1 = e0 + 16;       // 16..31
        float z0 = 0.0f, z1 = 0.0f, h0 = 0.0f, h1 = 0.0f;
        #pragma unroll 8
        for (int k = 0; k < HID; k++) {
            const float lz = Lz[k * HID + j];   // coalesced
            const float lh = Lh[k * HID + j];
            z0 += Wz[e0 * HID + k] * lz;        // warp-uniform broadcast
            z1 += Wz[e1 * HID + k] * lz;
            h0 += Wh[e0 * HID + k] * lh;
            h1 += Wh[e1 * HID + k] * lh;
        }
        g_MzT[j * EMBP + e0] = z0;
        g_MzT[j * EMBP + e1] = z1;
        g_MhT[j * EMBP + e0] = h0;
        g_MhT[j * EMBP + e1] = h1;
    }

    // Folded biases
    if (t < HID) {
        float cz = lbz[t], ch = lbh[t];
        #pragma unroll 8
        for (int k = 0; k < HID; k++) {
            cz += bz[k] * Lz[k * HID + t];
            ch += bh[k] * Lh[k * HID + t];
        }
        g_cz[t] = cz;
        g_ch[t] = ch;
    }

    // Softmax prefix table: warp 0, shuffle reduce + scan.
    if (t < 32) {
        const unsigned FULL = 0xffffffffu;
        float a0 = (t < Tt)      ? att[t]      : -1e30f;
        float a1 = (t + 32 < Tt) ? att[t + 32] : -1e30f;
        float m = fmaxf(a0, a1);
        #pragma unroll
        for (int off = 16; off > 0; off >>= 1)
            m = fmaxf(m, __shfl_xor_sync(FULL, m, off));
        float ex0 = (t < Tt)      ? __expf(a0 - m) : 0.0f;
        float ex1 = (t + 32 < Tt) ? __expf(a1 - m) : 0.0f;
        float s = ex0 + ex1;
        #pragma unroll
        for (int off = 16; off > 0; off >>= 1)
            s += __shfl_xor_sync(FULL, s, off);
        const float inv = 1.0f / s;

        // inclusive scan of ex0 across lanes
        float p0 = ex0;
        #pragma unroll
        for (int off = 1; off < 32; off <<= 1) {
            const float y = __shfl_up_sync(FULL, p0, off);
            if (t >= off) p0 += y;
        }
        const float tot0 = __shfl_sync(FULL, p0, 31);
        // inclusive scan of ex1
        float p1 = ex1;
        #pragma unroll
        for (int off = 1; off < 32; off <<= 1) {
            const float y = __shfl_up_sync(FULL, p1, off);
            if (t >= off) p1 += y;
        }
        if (t == 0) g_cumP[0] = 0.0f;
        g_cumP[t + 1] = p0 * inv;                               // entries 1..32
        if (t + 33 <= Tt) g_cumP[t + 33] = (tot0 + p1) * inv;   // entries 33..37
    }
}

// ---------------------------------------------------------------------------
// Main: one CTA (256 threads) per batch row.
//   pooled[b] = mean_n( w0*cell(ad[b]) + w1*cell(dis[b]) )   [H never stored]
//   cell(X)   = (1 - sigmoid(A@X@Mz + cz)) * tanh(A@X@Mh + ch)
//   out[b]    = relu(pooled @ Wc1 + bc1) @ Wc2 + bc2
//
// __launch_bounds__(256, 4): pins regs <= 64 -> 4 CTAs/SM -> one wave.
// ---------------------------------------------------------------------------
__global__ void __launch_bounds__(256, 4) main_kernel(
    const int*   __restrict__ x_batch,  // (B, C)
    const int*   __restrict__ LOS,      // (B,)
    const float* __restrict__ emb,      // (C, V, EMB)
    const float* __restrict__ Wc1,      // (HID, 2*HID)
    const float* __restrict__ bc1,      // (2*HID,)
    const float* __restrict__ Wc2,      // (2*HID, 1)
    const float* __restrict__ bc2,      // (1,)
    float*       __restrict__ out)      // (B, 1)
{
    __shared__ __align__(16) float sX[Cc][EMB];      // embeddings (ad 0..31, dis 32..63)
    __shared__ __align__(16) float sA[Nn][Nn];       // adjacency
    __shared__ __align__(16) float sMzT[HID][EMBP];  // folded weights, transposed+padded
    __shared__ __align__(16) float sMhT[HID][EMBP];
    __shared__ __align__(16) float sU[2][Nn][EMB];   // A @ X per branch
    __shared__ float sPool[4][HID];                  // per-group pool partials
    __shared__ float sPooled[HID];
    __shared__ float sRed[2 * HID];

    const int b = blockIdx.x;
    const int t = threadIdx.x;

    // Issue branch-weight loads FIRST so their latency overlaps staging.
    int L = LOS[b];
    L = min(max(L, 0), Tt);
    const float w0 = g_cumP[L];            // weight on 'ad' branch
    const float w1 = g_cumP[Tt] - w0;      // weight on 'dis' branch

    // Stage constants into shared, vectorized.
    // HID*EMBP = 2304 floats = 576 float4 per matrix.
    {
        const float4* gA4  = (const float4*)g_A;     // 256 float4
        const float4* gMz4 = (const float4*)g_MzT;   // 576 float4
        const float4* gMh4 = (const float4*)g_MhT;
        float4* sA4  = (float4*)&sA[0][0];
        float4* sMz4 = (float4*)&sMzT[0][0];
        float4* sMh4 = (float4*)&sMhT[0][0];
        sA4[t] = gA4[t];
        #pragma unroll
        for (int i = 0; i < 2; i++) {
            sMz4[t + 256 * i] = gMz4[t + 256 * i];
            sMh4[t + 256 * i] = gMh4[t + 256 * i];
        }
        if (t < 576 - 512) {
            sMz4[t + 512] = gMz4[t + 512];
            sMh4[t + 512] = gMh4[t + 512];
        }
    }

    // Gather embeddings: 512 float4, 2 per thread. Index loaded directly
    // (warp-broadcast LDG) -> no staging barrier needed before gather.
    {
        const float4* emb4 = (const float4*)emb;
        float4* sX4 = (float4*)&sX[0][0];
        #pragma unroll
        for (int i = 0; i < 2; i++) {
            const int o = t + 256 * i;        // 0..511
            const int c = o >> 3, q = o & 7;
            const int idx = x_batch[b * Cc + c];
            sX4[o] = emb4[(c * Vv + idx) * (EMB / 4) + q];
        }
    }
    __syncthreads();  // sX, sA, sM* ready

    // U = A @ X. Thread owns ONE branch (br = t>>7), TWO nodes (n0, n0+16),
    // one float4 column block q. Every X load is shared by both node rows:
    // X LDS.128 count halves vs the per-(n,q) mapping.
    {
        const int br = t >> 7;            // 0 or 1
        const int n0 = (t >> 3) & 15;     // nodes n0 and n0+16
        const int q  = t & 7;
        const float4* arow0 = (const float4*)&sA[n0][0];
        const float4* arow1 = (const float4*)&sA[n0 + 16][0];

        float4 acc0 = make_float4(0.0f, 0.0f, 0.0f, 0.0f);
        float4 acc1 = make_float4(0.0f, 0.0f, 0.0f, 0.0f);
        #pragma unroll
        for (int mt = 0; mt < 8; mt++) {
            const float4 a0 = arow0[mt];
            const float4 a1 = arow1[mt];
            #pragma unroll
            for (int mm = 0; mm < 4; mm++) {
                const float am0 = (mm == 0) ? a0.x : (mm == 1) ? a0.y
                                : (mm == 2) ? a0.z : a0.w;
                const float am1 = (mm == 0) ? a1.x : (mm == 1) ? a1.y
                                : (mm == 2) ? a1.z : a1.w;
                const float4 x4 = *(const float4*)&sX[br * Nn + mt * 4 + mm][4 * q];
                acc0.x += am0 * x4.x;  acc0.y += am0 * x4.y;
                acc0.z += am0 * x4.z;  acc0.w += am0 * x4.w;
                acc1.x += am1 * x4.x;  acc1.y += am1 * x4.y;
                acc1.z += am1 * x4.z;  acc1.w += am1 * x4.w;
            }
        }
        *(float4*)&sU[br][n0][4 * q]      = acc0;
        *(float4*)&sU[br][n0 + 16][4 * q] = acc1;
    }
    __syncthreads();  // sU ready

    // H phase fused with pooling: thread t -> column j = t&63,
    // nodes n = (t>>6) + 4i, i=0..7. M read as LDS.128 from the transposed
    // padded layout (conflict-free); U reads are warp-uniform broadcasts.
    {
        const int j  = t & 63;
        const int g  = t >> 6;
        const float cz = g_cz[j], ch = g_ch[j];
        float poolAcc = 0.0f;

        #pragma unroll
        for (int br = 0; br < 2; br++) {
            const float w = (br == 0) ? w0 : w1;
            float az[8], ah[8];
            #pragma unroll
            for (int i = 0; i < 8; i++) { az[i] = cz; ah[i] = ch; }

            #pragma unroll
            for (int kt = 0; kt < EMB / 4; kt++) {
                const int e0 = kt * 4;
                const float4 mz4 = *(const float4*)&sMzT[j][e0];
                const float4 mh4 = *(const float4*)&sMhT[j][e0];
                #pragma unroll
                for (int i = 0; i < 8; i++) {
                    const int n = g + 4 * i;
                    const float4 u4 = *(const float4*)&sU[br][n][e0];  // broadcast
                    az[i] += u4.x * mz4.x + u4.y * mz4.y + u4.z * mz4.z + u4.w * mz4.w;
                    ah[i] += u4.x * mh4.x + u4.y * mh4.y + u4.z * mh4.z + u4.w * mh4.w;
                }
            }

            #pragma unroll
            for (int i = 0; i < 8; i++) {
                // (1 - sigmoid(az)) = 1/(1+e^{az});  tanh(x) = 1 - 2/(1+e^{2x})
                const float omz = __fdividef(1.0f, 1.0f + __expf(az[i]));
                const float th  = 1.0f - __fdividef(2.0f, 1.0f + __expf(2.0f * ah[i]));
                poolAcc += w * omz * th;
            }
        }

        sPool[g][j] = poolAcc;
    }
    __syncthreads();  // sPool ready

    // pooled[j] = (sum of 4 group partials) / N
    if (t < HID) {
        sPooled[t] = (sPool[0][t] + sPool[1][t] + sPool[2][t] + sPool[3][t])
                     * (1.0f / (float)Nn);
    }
    __syncthreads();

    // classifier: hidden (128) -> scalar
    float partial = 0.0f;
    if (t < 2 * HID) {
        float h = bc1[t];
        #pragma unroll 8
        for (int j = 0; j < HID; j++)
            h += sPooled[j] * Wc1[j * (2 * HID) + t];
        partial = fmaxf(h, 0.0f) * Wc2[t];
    }
    if (t < 2 * HID) sRed[t] = partial;
    __syncthreads();

    if (t < 32) {
        float s = sRed[t] + sRed[t + 32] + sRed[t + 64] + sRed[t + 96];
        #pragma unroll
        for (int off = 16; off > 0; off >>= 1)
            s += __shfl_down_sync(0xFFFFFFFFu, s, off);
        if (t == 0) out[b] = s + bc2[0];
    }
}

// ---------------------------------------------------------------------------
// Launch
// ---------------------------------------------------------------------------
extern "C" void kernel_launch(void* const* d_in, const int* in_sizes, int n_in,
                              void* d_out, int out_size)
{
    const int*   x_batch = (const int*)  d_in[0];
    const int*   LOS     = (const int*)  d_in[1];
    const int*   edge    = (const int*)  d_in[2];
    const float* emb     = (const float*)d_in[3];
    const float* Wz      = (const float*)d_in[4];
    const float* bz      = (const float*)d_in[5];
    // d_in[6] = W_r, d_in[7] = b_r : dead (H0*R == 0 because H0 == 0)
    const float* Wh      = (const float*)d_in[8];
    const float* bh      = (const float*)d_in[9];
    const float* Lz      = (const float*)d_in[10];
    const float* lbz     = (const float*)d_in[11];
    // d_in[12] = L_r, d_in[13] = lb_r : dead
    const float* Lh      = (const float*)d_in[14];
    const float* lbh     = (const float*)d_in[15];
    const float* att     = (const float*)d_in[16];
    const float* Wc1     = (const float*)d_in[17];
    const float* bc1     = (const float*)d_in[18];
    const float* Wc2     = (const float*)d_in[19];
    const float* bc2     = (const float*)d_in[20];

    precompute_kernel<<<1, 1024>>>(edge, Wz, bz, Wh, bh, Lz, lbz, Lh, lbh, att);
    main_kernel<<<Bb, 256>>>(x_batch, LOS, emb, Wc1, bc1, Wc2, bc2, (float*)d_out);
}

// round 10
// speedup vs baseline: 1.5625x; 1.4366x over previous
#include <cuda_runtime.h>
#include <cuda_bf16.h>
#include <math.h>

// Problem constants
#define Bb   512
#define Cc   64
#define Nn   32
#define Vv   100
#define EMB  32
#define HID  64
#define Ee   256
#define Tt   37

// Precomputed tables
__device__ __align__(16) float g_AT[Nn * Nn];          // A^T: g_AT[m*32+n] = A[n][m]
__device__ __align__(16) float g_Mz[EMB * HID];        // W_z @ L_z[:HID], e-major
__device__ __align__(16) float g_Mh[EMB * HID];        // W_h @ L_h[:HID], e-major
__device__ __align__(16) float2 g_czh[HID];            // {cz_j, ch_j}
__device__ float g_cumP[Tt + 1];                       // prefix sums of softmax(att)
// G2[c][v][j][{z,h}]: per (channel, vocab) row of 64 interleaved z/h pairs (512B)
__device__ __align__(16) float g_G2[Cc * Vv * HID * 2];   // 3.27 MB

// packed f32x2 helpers
__device__ __forceinline__ void ffma2(unsigned long long& d,
                                      unsigned long long a,
                                      unsigned long long b) {
    asm("fma.rn.f32x2 %0, %1, %2, %0;" : "+l"(d) : "l"(a), "l"(b));
}
__device__ __forceinline__ unsigned long long pack_dup(float x) {
    unsigned long long r;
    asm("mov.b64 %0, {%1, %1};" : "=l"(r) : "f"(x));
    return r;
}
__device__ __forceinline__ void unpack2(float& lo, float& hi, unsigned long long v) {
    asm("mov.b64 {%0, %1}, %2;" : "=f"(lo), "=f"(hi) : "l"(v));
}

// ---------------------------------------------------------------------------
// Setup: grid 17 x 256. Block 0: A^T (int-atomic counts -> deterministic),
// folded biases, softmax prefix. Blocks 1..16: M = W @ L[:HID] slices,
// spread over 16 SMs so cold-DRAM latency overlaps chip-wide.
// ---------------------------------------------------------------------------
__global__ void __launch_bounds__(256) setup_kernel(
    const int*   __restrict__ edge,   // (2, E)
    const float* __restrict__ Wz, const float* __restrict__ bz,
    const float* __restrict__ Wh, const float* __restrict__ bh,
    const float* __restrict__ Lz, const float* __restrict__ lbz,
    const float* __restrict__ Lh, const float* __restrict__ lbh,
    const float* __restrict__ att)
{
    const int t = threadIdx.x;

    if (blockIdx.x == 0) {
        __shared__ int   sCnt[Nn * Nn];
        __shared__ int   sDeg[Nn];
        __shared__ float sDinv[Nn];

        for (int o = t; o < Nn * Nn; o += 256) sCnt[o] = 0;
        if (t < Nn) sDeg[t] = 0;
        __syncthreads();

        if (t < Ee) {   // one edge per thread (Ee == 256)
            const int s = edge[t];
            const int d = edge[Ee + t];
            atomicAdd(&sCnt[d * Nn + s], 1);
            atomicAdd(&sDeg[d], 1);
        }
        if (t < Nn) {   // self loop
            atomicAdd(&sCnt[t * Nn + t], 1);
            atomicAdd(&sDeg[t], 1);
        }
        __syncthreads();

        if (t < Nn) sDinv[t] = rsqrtf((float)sDeg[t]);   // deg >= 1 (self loop)
        __syncthreads();

        // A^T[m][n] = A[n][m] = cnt[dst=n][src=m] * dinv[m] * dinv[n]
        for (int o = t; o < Nn * Nn; o += 256) {
            const int m = o >> 5, n = o & 31;
            g_AT[o] = (float)sCnt[n * Nn + m] * sDinv[m] * sDinv[n];
        }

        // folded biases, packed {cz, ch}
        if (t < HID) {
            float cz = lbz[t], ch = lbh[t];
            #pragma unroll 8
            for (int k = 0; k < HID; k++) {
                cz += bz[k] * Lz[k * HID + t];
                ch += bh[k] * Lh[k * HID + t];
            }
            g_czh[t] = make_float2(cz, ch);
        }

        // softmax prefix (warp 0, shuffle scan)
        if (t < 32) {
            const unsigned FULL = 0xffffffffu;
            float a0 = (t < Tt)      ? att[t]      : -1e30f;
            float a1 = (t + 32 < Tt) ? att[t + 32] : -1e30f;
            float m = fmaxf(a0, a1);
            #pragma unroll
            for (int off = 16; off > 0; off >>= 1)
                m = fmaxf(m, __shfl_xor_sync(FULL, m, off));
            float ex0 = (t < Tt)      ? __expf(a0 - m) : 0.0f;
            float ex1 = (t + 32 < Tt) ? __expf(a1 - m) : 0.0f;
            float s = ex0 + ex1;
            #pragma unroll
            for (int off = 16; off > 0; off >>= 1)
                s += __shfl_xor_sync(FULL, s, off);
            const float inv = 1.0f / s;

            float p0 = ex0;
            #pragma unroll
            for (int off = 1; off < 32; off <<= 1) {
                const float y = __shfl_up_sync(FULL, p0, off);
                if (t >= off) p0 += y;
            }
            const float tot0 = __shfl_sync(FULL, p0, 31);
            float p1 = ex1;
            #pragma unroll
            for (int off = 1; off < 32; off <<= 1) {
                const float y = __shfl_up_sync(FULL, p1, off);
                if (t >= off) p1 += y;
            }
            if (t == 0) g_cumP[0] = 0.0f;
            g_cumP[t + 1] = p0 * inv;
            if (t + 33 <= Tt) g_cumP[t + 33] = (tot0 + p1) * inv;
        }
    } else {
        // M-GEMM slice: block bi handles e = 2*bi, 2*bi+1 for both matrices.
        const int bi  = blockIdx.x - 1;        // 0..15
        const int e   = 2 * bi + (t >> 7);     // one of 2 e-rows
        const int mat = (t >> 6) & 1;          // 0 = z, 1 = h
        const int j   = t & 63;
        const float* W  = mat ? Wh : Wz;
        const float* Lm = mat ? Lh : Lz;
        float acc = 0.0f;
        #pragma unroll 8
        for (int k = 0; k < HID; k++)
            acc += W[e * HID + k] * Lm[k * HID + j];   // W broadcast, L coalesced
        (mat ? g_Mh : g_Mz)[e * HID + j] = acc;
    }
}

// ---------------------------------------------------------------------------
// G2 build: grid 400 x 256, 16 (c,v) pairs per CTA.
// G2[c][v][j] = { sum_e emb[c,v,e]*Mz[e][j],  sum_e emb[c,v,e]*Mh[e][j] }
// ---------------------------------------------------------------------------
__global__ void __launch_bounds__(256) g2_kernel(
    const float* __restrict__ emb)    // (C, V, EMB)
{
    __shared__ __align__(16) float sMz[EMB * HID];   // 8 KB
    __shared__ __align__(16) float sMh[EMB * HID];
    __shared__ __align__(16) float sEmb[16][EMB];    // 2 KB

    const int t = threadIdx.x;

    // Stage M (coalesced float4)
    {
        float4* dMz = (float4*)sMz;  const float4* srcZ = (const float4*)g_Mz;
        float4* dMh = (float4*)sMh;  const float4* srcH = (const float4*)g_Mh;
        dMz[t] = srcZ[t];  dMz[t + 256] = srcZ[t + 256];
        dMh[t] = srcH[t];  dMh[t + 256] = srcH[t + 256];
    }
    // Stage 16 emb rows (float4; emb rows are 128B)
    if (t < 128) {
        const int p = t >> 3, q = t & 7;
        const int idx = blockIdx.x * 16 + p;       // idx = c*100+v
        ((float4*)&sEmb[p][0])[q] = ((const float4*)emb)[idx * (EMB / 4) + q];
    }
    __syncthreads();

    // 2048 outputs (16 pairs x 64 j x 2 mats), 8 per thread.
    // Warp-uniform (p, mat); j coalesced.
    #pragma unroll
    for (int i = 0; i < 8; i++) {
        const int o   = t + 256 * i;
        const int p   = o >> 7;
        const int mat = (o >> 6) & 1;
        const int j   = o & 63;
        const float* M = mat ? sMh : sMz;
        float acc = 0.0f;
        #pragma unroll
        for (int e = 0; e < EMB; e++)
            acc += sEmb[p][e] * M[e * HID + j];
        const int idx = blockIdx.x * 16 + p;
        g_G2[(idx * HID + j) * 2 + mat] = acc;
    }
}

// ---------------------------------------------------------------------------
// Main: one CTA (256 threads) per batch row.
// Gather 64 G2 rows (one per channel, by x index) -> ONE 32x64x32 GEMM
// with packed f32x2 FMAs -> fused sigmoid/tanh + pool (shuffle over nodes)
// -> classifier. Lane = node n, warp = 8-j block.
// ---------------------------------------------------------------------------
__global__ void __launch_bounds__(256, 4) main_kernel(
    const int*   __restrict__ x_batch,  // (B, C)
    const int*   __restrict__ LOS,      // (B,)
    const float* __restrict__ Wc1,      // (HID, 2*HID)
    const float* __restrict__ bc1,      // (2*HID,)
    const float* __restrict__ Wc2,      // (2*HID, 1)
    const float* __restrict__ bc2,      // (1,)
    float*       __restrict__ out)      // (B, 1)
{
    __shared__ __align__(16) float sG[Cc][HID * 2];  // 64 rows x 512B = 32 KB
    __shared__ __align__(16) float sAT[Nn * Nn];     // 4 KB
    __shared__ __align__(16) float2 sCzh[HID];
    __shared__ int   sIdx[Cc];
    __shared__ float sPooled[HID];
    __shared__ float sRed[2 * HID];

    const int b = blockIdx.x;
    const int t = threadIdx.x;
    const int n = t & 31;       // node lane
    const int w = t >> 5;       // warp -> j block [8w, 8w+8)

    // branch weights (early loads)
    int L = LOS[b];
    L = min(max(L, 0), Tt);
    const float w0 = g_cumP[L];
    const float w1 = g_cumP[Tt] - w0;

    // Stage A^T, czh, x indices
    ((float4*)sAT)[t] = ((const float4*)g_AT)[t];
    if (t < 32) ((float4*)sCzh)[t] = ((const float4*)g_czh)[t];
    if (t < Cc) sIdx[t] = x_batch[b * Cc + t];
    __syncthreads();   // sIdx ready

    // Gather 64 G2 rows: row r <-> channel c = r (ad = 0..31, dis = 32..63).
    // Each thread copies 128B (2 float4) of one row.
    {
        const int r  = t >> 2;
        const int qt = t & 3;
        const int v  = sIdx[r];
        const float4* src = (const float4*)&g_G2[(r * Vv + v) * HID * 2];
        float4* dst = (float4*)&sG[r][0];
        dst[qt * 8 + 0] = src[qt * 8 + 0];
        dst[qt * 8 + 1] = src[qt * 8 + 1];
        dst[qt * 8 + 2] = src[qt * 8 + 2];
        dst[qt * 8 + 3] = src[qt * 8 + 3];
        dst[qt * 8 + 4] = src[qt * 8 + 4];
        dst[qt * 8 + 5] = src[qt * 8 + 5];
        dst[qt * 8 + 6] = src[qt * 8 + 6];
        dst[qt * 8 + 7] = src[qt * 8 + 7];
    }
    __syncthreads();   // sG, sAT, sCzh ready

    // Hoist packed bias inits {cz_j, ch_j} for this warp's 8 j's
    unsigned long long czh[8];
    #pragma unroll
    for (int jj = 0; jj < 8; jj++)
        czh[jj] = *(const unsigned long long*)&sCzh[8 * w + jj];

    float pool[8];
    #pragma unroll
    for (int jj = 0; jj < 8; jj++) pool[jj] = 0.0f;

    #pragma unroll
    for (int br = 0; br < 2; br++) {
        const float wgt = (br == 0) ? w0 : w1;
        unsigned long long acc[8];
        #pragma unroll
        for (int jj = 0; jj < 8; jj++) acc[jj] = czh[jj];

        #pragma unroll
        for (int m = 0; m < Nn; m++) {
            const float a = sAT[m * Nn + n];            // coalesced LDS
            const unsigned long long ad = pack_dup(a);
            const ulonglong2* gp =
                (const ulonglong2*)&sG[br * Nn + m][16 * w];  // warp-broadcast
            ulonglong2 q0 = gp[0];
            ulonglong2 q1 = gp[1];
            ffma2(acc[0], ad, q0.x);  ffma2(acc[1], ad, q0.y);
            ffma2(acc[2], ad, q1.x);  ffma2(acc[3], ad, q1.y);
            ulonglong2 q2 = gp[2];
            ulonglong2 q3 = gp[3];
            ffma2(acc[4], ad, q2.x);  ffma2(acc[5], ad, q2.y);
            ffma2(acc[6], ad, q3.x);  ffma2(acc[7], ad, q3.y);
        }

        #pragma unroll
        for (int jj = 0; jj < 8; jj++) {
            float az, ah;
            unpack2(az, ah, acc[jj]);
            // (1 - sigmoid(az)) = 1/(1+e^az); tanh(x) = 1 - 2/(1+e^{2x})
            const float omz = __fdividef(1.0f, 1.0f + __expf(az));
            const float th  = 1.0f - __fdividef(2.0f, 1.0f + __expf(2.0f * ah));
            pool[jj] += wgt * omz * th;
        }
    }

    // Pool over nodes = sum over the 32 lanes, per j.
    #pragma unroll
    for (int jj = 0; jj < 8; jj++) {
        float s = pool[jj];
        #pragma unroll
        for (int off = 16; off > 0; off >>= 1)
            s += __shfl_xor_sync(0xffffffffu, s, off);
        if (n == 0) sPooled[8 * w + jj] = s * (1.0f / (float)Nn);
    }
    __syncthreads();   // sPooled ready

    // classifier: hidden (128) -> scalar
    float partial = 0.0f;
    if (t < 2 * HID) {
        float h = bc1[t];
        #pragma unroll 8
        for (int j = 0; j < HID; j++)
            h += sPooled[j] * Wc1[j * (2 * HID) + t];
        partial = fmaxf(h, 0.0f) * Wc2[t];
    }
    if (t < 2 * HID) sRed[t] = partial;
    __syncthreads();

    if (t < 32) {
        float s = sRed[t] + sRed[t + 32] + sRed[t + 64] + sRed[t + 96];
        #pragma unroll
        for (int off = 16; off > 0; off >>= 1)
            s += __shfl_down_sync(0xffffffffu, s, off);
        if (t == 0) out[b] = s + bc2[0];
    }
}

// ---------------------------------------------------------------------------
// Launch
// ---------------------------------------------------------------------------
extern "C" void kernel_launch(void* const* d_in, const int* in_sizes, int n_in,
                              void* d_out, int out_size)
{
    const int*   x_batch = (const int*)  d_in[0];
    const int*   LOS     = (const int*)  d_in[1];
    const int*   edge    = (const int*)  d_in[2];
    const float* emb     = (const float*)d_in[3];
    const float* Wz      = (const float*)d_in[4];
    const float* bz      = (const float*)d_in[5];
    // d_in[6] = W_r, d_in[7] = b_r : dead (H0 == 0 -> H0*R == 0)
    const float* Wh      = (const float*)d_in[8];
    const float* bh      = (const float*)d_in[9];
    const float* Lz      = (const float*)d_in[10];
    const float* lbz     = (const float*)d_in[11];
    // d_in[12] = L_r, d_in[13] = lb_r : dead
    const float* Lh      = (const float*)d_in[14];
    const float* lbh     = (const float*)d_in[15];
    const float* att     = (const float*)d_in[16];
    const float* Wc1     = (const float*)d_in[17];
    const float* bc1     = (const float*)d_in[18];
    const float* Wc2     = (const float*)d_in[19];
    const float* bc2     = (const float*)d_in[20];

    setup_kernel<<<17, 256>>>(edge, Wz, bz, Wh, bh, Lz, lbz, Lh, lbh, att);
    g2_kernel<<<(Cc * Vv) / 16, 256>>>(emb);
    main_kernel<<<Bb, 256>>>(x_batch, LOS, Wc1, bc1, Wc2, bc2, (float*)d_out);
}